// round 6
// baseline (speedup 1.0000x reference)
#include <cuda_runtime.h>
#include <math.h>

#define BB 8
#define LL 8192
#define CCH 256
#define NN 512
#define KK 16
#define FMINF 1.17549435e-38f

// scratch (no allocations allowed)
__device__ float g_w[BB * NN];    // FTZ proto_weights
__device__ float g_t[BB * NN];    // log(w), -inf where 0
__device__ float g_pn2[NN];       // |p_n|^2
__device__ float g_qq[BB * LL];   // |q_l|^2

__device__ __forceinline__ float warp_maxf(float v) {
    #pragma unroll
    for (int o = 16; o; o >>= 1) v = fmaxf(v, __shfl_xor_sync(0xffffffffu, v, o));
    return v;
}
__device__ __forceinline__ float warp_sumf(float v) {
    #pragma unroll
    for (int o = 16; o; o >>= 1) v += __shfl_xor_sync(0xffffffffu, v, o);
    return v;
}
__device__ __forceinline__ double warp_sumd(double v) {
    #pragma unroll
    for (int o = 16; o; o >>= 1) v += __shfl_xor_sync(0xffffffffu, v, o);
    return v;
}

// ---- packed f32x2 helpers (Blackwell FFMA2) ----
__device__ __forceinline__ void ffma2(unsigned long long& d,
                                      unsigned long long a,
                                      unsigned long long b) {
    asm("fma.rn.f32x2 %0, %1, %2, %0;" : "+l"(d) : "l"(a), "l"(b));
}
__device__ __forceinline__ unsigned long long pack2(float x) {
    unsigned long long r;
    asm("mov.b64 %0, {%1, %1};" : "=l"(r) : "f"(x));
    return r;
}
__device__ __forceinline__ void unpack2(unsigned long long v, float& lo, float& hi) {
    asm("mov.b64 {%0, %1}, %2;" : "=f"(lo), "=f"(hi) : "l"(v));
}

// ---------------------------------------------------------------------------
// Per-batch proto weights, FTZ semantics (warp-per-n coalesced dot phase).
// ---------------------------------------------------------------------------
__global__ void prep_w_kernel(const float* __restrict__ P,
                              const float* __restrict__ gt) {
    int b = blockIdx.x;
    int tid = threadIdx.x;
    int lane = tid & 31, wid = tid >> 5;
    __shared__ double gsd[CCH];
    __shared__ float xs[NN];
    __shared__ float redf[256];
    __shared__ double redd[256];
    __shared__ float sXmax, sZw;

    if (tid < CCH) {
        double s = 0.0;
        #pragma unroll
        for (int k = 0; k < KK; k++) s += (double)gt[(b * KK + k) * CCH + tid];
        gsd[tid] = (double)__fdiv_rn((float)s, 16.0f);
    }
    __syncthreads();

    for (int n = wid; n < NN; n += 8) {
        const float4* pr4 = (const float4*)(P + n * CCH);
        float4 v0 = pr4[lane];
        float4 v1 = pr4[lane + 32];
        int c0 = lane * 4, c1 = 128 + lane * 4;
        double a = 0.0;
        a = fma((double)v0.x, gsd[c0 + 0], a);
        a = fma((double)v0.y, gsd[c0 + 1], a);
        a = fma((double)v0.z, gsd[c0 + 2], a);
        a = fma((double)v0.w, gsd[c0 + 3], a);
        a = fma((double)v1.x, gsd[c1 + 0], a);
        a = fma((double)v1.y, gsd[c1 + 1], a);
        a = fma((double)v1.z, gsd[c1 + 2], a);
        a = fma((double)v1.w, gsd[c1 + 3], a);
        a = warp_sumd(a);
        if (lane == 0) xs[n] = __fdiv_rn((float)a, 0.1f);
    }
    __syncthreads();

    {   // block max
        float m = -INFINITY;
        for (int n = tid; n < NN; n += blockDim.x) m = fmaxf(m, xs[n]);
        redf[tid] = m;
        __syncthreads();
        for (int s = 128; s; s >>= 1) {
            if (tid < s) redf[tid] = fmaxf(redf[tid], redf[tid + s]);
            __syncthreads();
        }
        if (tid == 0) sXmax = redf[0];
        __syncthreads();
    }
    float X = sXmax;

    {   // Zw = f32(sum of flushed exps)
        double z = 0.0;
        for (int n = tid; n < NN; n += blockDim.x) {
            float e = expf(__fsub_rn(xs[n], X));
            if (e >= FMINF) z += (double)e;
        }
        redd[tid] = z;
        __syncthreads();
        for (int s = 128; s; s >>= 1) {
            if (tid < s) redd[tid] += redd[tid + s];
            __syncthreads();
        }
        if (tid == 0) sZw = (float)redd[0];
        __syncthreads();
    }
    float Zw = sZw;

    for (int n = tid; n < NN; n += blockDim.x) {
        float e = expf(__fsub_rn(xs[n], X));
        if (e < FMINF) e = 0.f;
        float w = __fdiv_rn(e, Zw);
        if (w < FMINF) w = 0.f;
        g_w[b * NN + n] = w;
        g_t[b * NN + n] = (w > 0.f) ? logf(w) : -INFINITY;
    }
}

__global__ void prep_pn2_kernel(const float* __restrict__ P) {
    int lane = threadIdx.x & 31, wid = threadIdx.x >> 5;
    int n = blockIdx.x * 8 + wid;
    const float4* pr4 = (const float4*)(P + n * CCH);
    float4 a = pr4[lane];
    float4 c = pr4[lane + 32];
    float s = a.x * a.x + a.y * a.y + a.z * a.z + a.w * a.w
            + c.x * c.x + c.y * c.y + c.z * c.z + c.w * c.w;
    s = warp_sumf(s);
    if (lane == 0) g_pn2[n] = s;
}

__global__ void prep_qq_kernel(const float* __restrict__ Q) {
    int wid = threadIdx.x >> 5, lane = threadIdx.x & 31;
    int row = blockIdx.x * 8 + wid;
    const float4* q4 = (const float4*)Q + (size_t)row * (CCH / 4);
    float4 a = q4[lane];
    float4 c = q4[lane + 32];
    float s = a.x * a.x + a.y * a.y + a.z * a.z + a.w * a.w
            + c.x * c.x + c.y * c.y + c.z * c.z + c.w * c.w;
    s = warp_sumf(s);
    if (lane == 0) g_qq[row] = s;
}

// ---------------------------------------------------------------------------
// Main kernel: block = 32 queries x 512 protos; 8 warps = 4 L-groups x 2 N-halves.
// Warp = 8 queries x 256 protos; thread = 8L x 8N (FFMA2).
// n(j) = nh*256 + (j>>2)*128 + lane*4 + (j&3).
// Epilogue: 2-warp phased combine, FTZ chain identical to round-4 semantics.
// ---------------------------------------------------------------------------
__global__ void __launch_bounds__(256, 2)
match_kernel(const float* __restrict__ Q, const float* __restrict__ P,
             float* __restrict__ out) {
    __shared__ __align__(16) float p_s[16][516];   // 33 KB
    __shared__ __align__(16) float q_s[16][36];    // 2.3 KB
    __shared__ float wS[NN], tS[NN], pn2S[NN];     // 6 KB
    // epilogue combine buffers
    __shared__ float dmS[2][32];
    __shared__ double zaS[2][32];
    __shared__ float kmS[2][32];
    __shared__ float bpS[2][32];
    __shared__ int bnS[2][32];
    __shared__ float bdS[2][32];

    int tid = threadIdx.x;
    int b = blockIdx.y;
    int l0 = blockIdx.x * 32;
    int lane = tid & 31, w = tid >> 5;
    int lg = w & 3;          // L-group: rows lg*8 .. lg*8+7
    int nh = w >> 2;         // N-half: protos nh*256 .. +255

    for (int i = tid; i < NN; i += 256) {
        wS[i] = g_w[b * NN + i];
        tS[i] = g_t[b * NN + i];
        pn2S[i] = g_pn2[i];
    }

    const float* Qb = Q + (size_t)(b * LL + l0) * CCH;

    unsigned long long acc2[8][4];
    #pragma unroll
    for (int i = 0; i < 8; i++)
        #pragma unroll
        for (int m = 0; m < 4; m++) acc2[i][m] = 0ULL;

    int nbase = nh * 256 + lane * 4;

    for (int cc = 0; cc < CCH; cc += 16) {
        #pragma unroll
        for (int r = 0; r < 8; r++) {
            int idx = tid + r * 256;
            int n = idx >> 2, f = idx & 3;
            float4 v = *(const float4*)(P + n * CCH + cc + f * 4);
            p_s[f * 4 + 0][n] = v.x;
            p_s[f * 4 + 1][n] = v.y;
            p_s[f * 4 + 2][n] = v.z;
            p_s[f * 4 + 3][n] = v.w;
        }
        if (tid < 128) {
            int l = tid >> 2, f = tid & 3;
            float4 v = *(const float4*)(Qb + l * CCH + cc + f * 4);
            q_s[f * 4 + 0][l] = v.x;
            q_s[f * 4 + 1][l] = v.y;
            q_s[f * 4 + 2][l] = v.z;
            q_s[f * 4 + 3][l] = v.w;
        }
        __syncthreads();
        #pragma unroll
        for (int c = 0; c < 16; c++) {
            float4 qv0 = *(const float4*)(&q_s[c][lg * 8]);
            float4 qv1 = *(const float4*)(&q_s[c][lg * 8 + 4]);
            unsigned long long qd[8];
            qd[0] = pack2(qv0.x); qd[1] = pack2(qv0.y);
            qd[2] = pack2(qv0.z); qd[3] = pack2(qv0.w);
            qd[4] = pack2(qv1.x); qd[5] = pack2(qv1.y);
            qd[6] = pack2(qv1.z); qd[7] = pack2(qv1.w);
            ulonglong2 pA = *(const ulonglong2*)(&p_s[c][nbase]);
            ulonglong2 pB = *(const ulonglong2*)(&p_s[c][nbase + 128]);
            #pragma unroll
            for (int i = 0; i < 8; i++) {
                ffma2(acc2[i][0], qd[i], pA.x);
                ffma2(acc2[i][1], qd[i], pA.y);
                ffma2(acc2[i][2], qd[i], pB.x);
                ffma2(acc2[i][3], qd[i], pB.y);
            }
        }
        __syncthreads();
    }

    // ================= epilogue =================
    // Phase 1: per-row local dmax
    #pragma unroll 1
    for (int i = 0; i < 8; i++) {
        float av[8];
        #pragma unroll
        for (int m = 0; m < 4; m++) unpack2(acc2[i][m], av[2 * m], av[2 * m + 1]);
        float dm = av[0];
        #pragma unroll
        for (int j = 1; j < 8; j++) dm = fmaxf(dm, av[j]);
        dm = warp_maxf(dm);
        if (lane == 0) dmS[nh][lg * 8 + i] = dm;
    }
    __syncthreads();

    // Phase 2: Za partial (double) and kmax partial
    #pragma unroll 1
    for (int i = 0; i < 8; i++) {
        int r = lg * 8 + i;
        float dmax = fmaxf(dmS[0][r], dmS[1][r]);
        float Xf = __fdiv_rn(dmax, 0.1f);
        float av[8];
        #pragma unroll
        for (int m = 0; m < 4; m++) unpack2(acc2[i][m], av[2 * m], av[2 * m + 1]);
        double zs = 0.0;
        float km = -INFINITY;
        #pragma unroll
        for (int j = 0; j < 8; j++) {
            if (av[j] > dmax - 8.8f) {
                float x = __fdiv_rn(av[j], 0.1f);
                float e = expf(__fsub_rn(x, Xf));
                if (e >= FMINF) zs += (double)e;
            }
            int n = nh * 256 + ((j >> 2) * 128) + (lane * 4) + (j & 3);
            km = fmaxf(km, fmaf(av[j] - dmax, 10.0f, tS[n]));
        }
        zs = warp_sumd(zs);
        km = warp_maxf(km);
        if (lane == 0) { zaS[nh][r] = zs; kmS[nh][r] = km; }
    }
    __syncthreads();

    // Phase 3: candidate scan with global Za / kmax
    #pragma unroll 1
    for (int i = 0; i < 8; i++) {
        int r = lg * 8 + i;
        float dmax = fmaxf(dmS[0][r], dmS[1][r]);
        float Xf = __fdiv_rn(dmax, 0.1f);
        float Za = (float)(zaS[0][r] + zaS[1][r]);
        float kmax = fmaxf(kmS[0][r], kmS[1][r]);

        float av[8];
        #pragma unroll
        for (int m = 0; m < 4; m++) unpack2(acc2[i][m], av[2 * m], av[2 * m + 1]);

        // seeds: nh==0 carries the n=0 fallback (dot held by lane 0, j 0)
        int bn = (nh == 0) ? 0 : 0x7FFFFFFF;
        float bp = 0.f;
        float bd = (nh == 0) ? __shfl_sync(0xffffffffu, av[0], 0) : 0.f;

        if (kmax >= -87.4f) {
            float thr = kmax - 0.02f;
            float key[8];
            #pragma unroll
            for (int j = 0; j < 8; j++) {
                int n = nh * 256 + ((j >> 2) * 128) + (lane * 4) + (j & 3);
                key[j] = fmaf(av[j] - dmax, 10.0f, tS[n]);
            }
            #pragma unroll 1
            for (int j = 0; j < 8; j++) {
                unsigned msk = __ballot_sync(0xffffffffu, key[j] >= thr);
                while (msk) {
                    int ln = __ffs(msk) - 1;
                    msk &= msk - 1;
                    int n = nh * 256 + ((j >> 2) * 128) + (ln * 4) + (j & 3);
                    float Ac = __shfl_sync(0xffffffffu, av[j], ln);
                    float x = __fdiv_rn(Ac, 0.1f);
                    float e = expf(__fsub_rn(x, Xf));
                    if (e < FMINF) e = 0.f;
                    float s = __fdiv_rn(e, Za);
                    if (s < FMINF) s = 0.f;
                    float p = __fmul_rn(s, wS[n]);
                    if (p < FMINF) p = 0.f;
                    if (p > bp || (p == bp && p > 0.f && n < bn)) {
                        bp = p; bn = n; bd = Ac;
                    }
                }
            }
        }
        if (lane == 0) { bpS[nh][r] = bp; bnS[nh][r] = bn; bdS[nh][r] = bd; }
    }
    __syncthreads();

    // Phase 4: combine halves, compute rd, write
    if (tid < 32) {
        int r = tid;
        float p0 = bpS[0][r], p1 = bpS[1][r];
        int n0 = bnS[0][r], n1 = bnS[1][r];
        float d0 = bdS[0][r], d1 = bdS[1][r];
        float bp = p0; int bn = n0; float bd = d0;
        if (p1 > p0 || (p1 == p0 && p1 > 0.f && n1 < n0)) { bp = p1; bn = n1; bd = d1; }
        int l = l0 + r;
        float rd = fmaf(-2.0f, bd, g_qq[(size_t)b * LL + l]) + pn2S[bn];
        out[(size_t)b * LL + l] = rd;
    }
}

// ---------------------------------------------------------------------------
extern "C" void kernel_launch(void* const* d_in, const int* in_sizes, int n_in,
                              void* d_out, int out_size) {
    const float* Q = nullptr;
    const float* P = nullptr;
    const float* G = nullptr;
    for (int i = 0; i < n_in; i++) {
        if (in_sizes[i] == BB * LL * CCH) Q = (const float*)d_in[i];
        else if (in_sizes[i] == NN * CCH) P = (const float*)d_in[i];
        else if (in_sizes[i] == BB * KK * CCH) G = (const float*)d_in[i];
    }
    float* out = (float*)d_out;

    prep_w_kernel<<<BB, 256>>>(P, G);
    prep_pn2_kernel<<<NN / 8, 256>>>(P);
    prep_qq_kernel<<<BB * LL / 8, 256>>>(Q);
    dim3 grid(LL / 32, BB);
    match_kernel<<<grid, 256>>>(Q, P, out);
}

// round 8
// speedup vs baseline: 1.5151x; 1.5151x over previous
#include <cuda_runtime.h>
#include <math.h>

#define BB 8
#define LL 8192
#define CCH 256
#define NN 512
#define KK 16
#define FMINF 1.17549435e-38f

// scratch (no allocations allowed)
__device__ float g_w[BB * NN];    // FTZ proto_weights
__device__ float g_t[BB * NN];    // log(w), -inf where 0 (prep only)
__device__ float g_pn2[NN];       // |p_n|^2
__device__ float g_qq[BB * LL];   // |q_l|^2

__device__ __forceinline__ float warp_maxf(float v) {
    #pragma unroll
    for (int o = 16; o; o >>= 1) v = fmaxf(v, __shfl_xor_sync(0xffffffffu, v, o));
    return v;
}
__device__ __forceinline__ float warp_sumf(float v) {
    #pragma unroll
    for (int o = 16; o; o >>= 1) v += __shfl_xor_sync(0xffffffffu, v, o);
    return v;
}
__device__ __forceinline__ double warp_sumd(double v) {
    #pragma unroll
    for (int o = 16; o; o >>= 1) v += __shfl_xor_sync(0xffffffffu, v, o);
    return v;
}

// m16n8k8 TF32 mma (row.col). Raw f32 bits as tf32 (truncation) — candidate
// filter only; margins cover the error.
__device__ __forceinline__ void mma_tf32(float& c0, float& c1, float& c2, float& c3,
                                         float a0, float a1, float a2, float a3,
                                         float b0, float b1) {
    asm volatile(
        "mma.sync.aligned.m16n8k8.row.col.f32.tf32.tf32.f32 "
        "{%0,%1,%2,%3}, {%4,%5,%6,%7}, {%8,%9}, {%0,%1,%2,%3};"
        : "+f"(c0), "+f"(c1), "+f"(c2), "+f"(c3)
        : "r"(__float_as_uint(a0)), "r"(__float_as_uint(a1)),
          "r"(__float_as_uint(a2)), "r"(__float_as_uint(a3)),
          "r"(__float_as_uint(b0)), "r"(__float_as_uint(b1)));
}

// exact f32 warp dot of two 256-float rows (float4 per lane x2)
__device__ __forceinline__ float warp_dot256(const float4* q4, const float4* p4,
                                             int lane) {
    float4 qa = q4[lane], qb = q4[lane + 32];
    float4 pa = p4[lane], pb = p4[lane + 32];
    float s = 0.f;
    s = fmaf(qa.x, pa.x, s); s = fmaf(qa.y, pa.y, s);
    s = fmaf(qa.z, pa.z, s); s = fmaf(qa.w, pa.w, s);
    s = fmaf(qb.x, pb.x, s); s = fmaf(qb.y, pb.y, s);
    s = fmaf(qb.z, pb.z, s); s = fmaf(qb.w, pb.w, s);
    return warp_sumf(s);
}

// ---------------------------------------------------------------------------
// prep kernels (unchanged)
// ---------------------------------------------------------------------------
__global__ void prep_w_kernel(const float* __restrict__ P,
                              const float* __restrict__ gt) {
    int b = blockIdx.x;
    int tid = threadIdx.x;
    int lane = tid & 31, wid = tid >> 5;
    __shared__ double gsd[CCH];
    __shared__ float xs[NN];
    __shared__ float redf[256];
    __shared__ double redd[256];
    __shared__ float sXmax, sZw;

    if (tid < CCH) {
        double s = 0.0;
        #pragma unroll
        for (int k = 0; k < KK; k++) s += (double)gt[(b * KK + k) * CCH + tid];
        gsd[tid] = (double)__fdiv_rn((float)s, 16.0f);
    }
    __syncthreads();

    for (int n = wid; n < NN; n += 8) {
        const float4* pr4 = (const float4*)(P + n * CCH);
        float4 v0 = pr4[lane];
        float4 v1 = pr4[lane + 32];
        int c0 = lane * 4, c1 = 128 + lane * 4;
        double a = 0.0;
        a = fma((double)v0.x, gsd[c0 + 0], a);
        a = fma((double)v0.y, gsd[c0 + 1], a);
        a = fma((double)v0.z, gsd[c0 + 2], a);
        a = fma((double)v0.w, gsd[c0 + 3], a);
        a = fma((double)v1.x, gsd[c1 + 0], a);
        a = fma((double)v1.y, gsd[c1 + 1], a);
        a = fma((double)v1.z, gsd[c1 + 2], a);
        a = fma((double)v1.w, gsd[c1 + 3], a);
        a = warp_sumd(a);
        if (lane == 0) xs[n] = __fdiv_rn((float)a, 0.1f);
    }
    __syncthreads();

    {
        float m = -INFINITY;
        for (int n = tid; n < NN; n += blockDim.x) m = fmaxf(m, xs[n]);
        redf[tid] = m;
        __syncthreads();
        for (int s = 128; s; s >>= 1) {
            if (tid < s) redf[tid] = fmaxf(redf[tid], redf[tid + s]);
            __syncthreads();
        }
        if (tid == 0) sXmax = redf[0];
        __syncthreads();
    }
    float X = sXmax;

    {
        double z = 0.0;
        for (int n = tid; n < NN; n += blockDim.x) {
            float e = expf(__fsub_rn(xs[n], X));
            if (e >= FMINF) z += (double)e;
        }
        redd[tid] = z;
        __syncthreads();
        for (int s = 128; s; s >>= 1) {
            if (tid < s) redd[tid] += redd[tid + s];
            __syncthreads();
        }
        if (tid == 0) sZw = (float)redd[0];
        __syncthreads();
    }
    float Zw = sZw;

    for (int n = tid; n < NN; n += blockDim.x) {
        float e = expf(__fsub_rn(xs[n], X));
        if (e < FMINF) e = 0.f;
        float w = __fdiv_rn(e, Zw);
        if (w < FMINF) w = 0.f;
        g_w[b * NN + n] = w;
        g_t[b * NN + n] = (w > 0.f) ? logf(w) : -INFINITY;
    }
}

__global__ void prep_pn2_kernel(const float* __restrict__ P) {
    int lane = threadIdx.x & 31, wid = threadIdx.x >> 5;
    int n = blockIdx.x * 8 + wid;
    const float4* pr4 = (const float4*)(P + n * CCH);
    float4 a = pr4[lane];
    float4 c = pr4[lane + 32];
    float s = a.x * a.x + a.y * a.y + a.z * a.z + a.w * a.w
            + c.x * c.x + c.y * c.y + c.z * c.z + c.w * c.w;
    s = warp_sumf(s);
    if (lane == 0) g_pn2[n] = s;
}

__global__ void prep_qq_kernel(const float* __restrict__ Q) {
    int wid = threadIdx.x >> 5, lane = threadIdx.x & 31;
    int row = blockIdx.x * 8 + wid;
    const float4* q4 = (const float4*)Q + (size_t)row * (CCH / 4);
    float4 a = q4[lane];
    float4 c = q4[lane + 32];
    float s = a.x * a.x + a.y * a.y + a.z * a.z + a.w * a.w
            + c.x * c.x + c.y * c.y + c.z * c.z + c.w * c.w;
    s = warp_sumf(s);
    if (lane == 0) g_qq[row] = s;
}

// ---------------------------------------------------------------------------
// Main kernel: TF32 mma filter + exact f32 candidate refinement.
// Block = 64 rows x 512 protos, 512 threads (16 warps = 2 L-halves x 8 N-octs).
// Candidate rule: approx dot within 9.4 of approx max (captures every proto
// whose product can survive FTZ: cutoff 8.734 + 2x TF32 error bound 0.2).
// Overflow (>NCAND) -> full exact 512-proto scan for that row (p_s reused).
// ---------------------------------------------------------------------------
#define NCAND 64

struct SmemT {
    float p_s[NN][20];       // swizzled P chunk; reused as dot scratch in ovf path
    float q_s[64][20];
    float wS[NN], pn2S[NN];
    float dmS[8][64];
    int   cnt[64];
    int   cand_n[64][NCAND];
    float candd[64][NCAND];
};

__global__ void __launch_bounds__(512, 1)
match_kernel(const float* __restrict__ Q, const float* __restrict__ P,
             float* __restrict__ out) {
    extern __shared__ char smem_raw[];
    SmemT& S = *(SmemT*)smem_raw;

    int tid = threadIdx.x;
    int lane = tid & 31, w = tid >> 5;
    int lh = w & 1;
    int nq = w >> 1;
    int g = lane >> 2, q = lane & 3;

    int R0 = blockIdx.x * 64;
    int b = R0 >> 13;

    if (tid < NN) {
        S.wS[tid] = g_w[b * NN + tid];
        S.pn2S[tid] = g_pn2[tid];
    }
    if (tid < 64) { S.cnt[tid] = 1; S.cand_n[tid][0] = 0; }

    const float* Qb = Q + (size_t)R0 * CCH;

    float acc[2][8][4];
    #pragma unroll
    for (int ms = 0; ms < 2; ms++)
        #pragma unroll
        for (int ns = 0; ns < 8; ns++)
            #pragma unroll
            for (int e = 0; e < 4; e++) acc[ms][ns][e] = 0.f;

    for (int cc = 0; cc < CCH; cc += 16) {
        #pragma unroll
        for (int r = 0; r < 4; r++) {
            int idx = tid + r * 512;
            int n = idx >> 2, f = idx & 3;
            float4 v = *(const float4*)(P + n * CCH + cc + 4 * f);
            int sr = (n >> 3) & 3;
            S.p_s[n][((0 + sr) & 3) * 4 + f] = v.x;
            S.p_s[n][((1 + sr) & 3) * 4 + f] = v.y;
            S.p_s[n][((2 + sr) & 3) * 4 + f] = v.z;
            S.p_s[n][((3 + sr) & 3) * 4 + f] = v.w;
        }
        if (tid < 256) {
            int l = tid >> 2, f = tid & 3;
            float4 v = *(const float4*)(Qb + l * CCH + cc + 4 * f);
            int sr = (l >> 3) & 3;
            S.q_s[l][((0 + sr) & 3) * 4 + f] = v.x;
            S.q_s[l][((1 + sr) & 3) * 4 + f] = v.y;
            S.q_s[l][((2 + sr) & 3) * 4 + f] = v.z;
            S.q_s[l][((3 + sr) & 3) * 4 + f] = v.w;
        }
        __syncthreads();

        float4 A[2][2];
        #pragma unroll
        for (int ms = 0; ms < 2; ms++)
            #pragma unroll
            for (int h = 0; h < 2; h++) {
                int row = lh * 32 + ms * 16 + 8 * h + g;
                int sr = (row >> 3) & 3;
                A[ms][h] = *(const float4*)&S.q_s[row][((q + sr) & 3) * 4];
            }
        #pragma unroll
        for (int ns = 0; ns < 8; ns++) {
            int n = nq * 64 + ns * 8 + g;
            int sr = (n >> 3) & 3;
            float4 Bv = *(const float4*)&S.p_s[n][((q + sr) & 3) * 4];
            #pragma unroll
            for (int ms = 0; ms < 2; ms++) {
                mma_tf32(acc[ms][ns][0], acc[ms][ns][1], acc[ms][ns][2], acc[ms][ns][3],
                         A[ms][0].x, A[ms][1].x, A[ms][0].y, A[ms][1].y, Bv.x, Bv.y);
                mma_tf32(acc[ms][ns][0], acc[ms][ns][1], acc[ms][ns][2], acc[ms][ns][3],
                         A[ms][0].z, A[ms][1].z, A[ms][0].w, A[ms][1].w, Bv.z, Bv.w);
            }
        }
        __syncthreads();
    }

    // ---- Phase 1: per-(octant,row) local max of approx dot ----
    #pragma unroll
    for (int ms = 0; ms < 2; ms++)
        #pragma unroll
        for (int h = 0; h < 2; h++) {
            int r = lh * 32 + ms * 16 + 8 * h + g;
            float vm = -INFINITY;
            #pragma unroll
            for (int ns = 0; ns < 8; ns++)
                #pragma unroll
                for (int e = 0; e < 2; e++)
                    vm = fmaxf(vm, acc[ms][ns][2 * h + e]);
            vm = fmaxf(vm, __shfl_xor_sync(0xffffffffu, vm, 1));
            vm = fmaxf(vm, __shfl_xor_sync(0xffffffffu, vm, 2));
            if (q == 0) S.dmS[nq][r] = vm;
        }
    __syncthreads();

    // ---- Phase 2: candidate push (dthr rule only) ----
    #pragma unroll
    for (int ms = 0; ms < 2; ms++)
        #pragma unroll
        for (int h = 0; h < 2; h++) {
            int r = lh * 32 + ms * 16 + 8 * h + g;
            float gdm = -INFINITY;
            #pragma unroll
            for (int o = 0; o < 8; o++) gdm = fmaxf(gdm, S.dmS[o][r]);
            float dthr = gdm - 9.4f;
            #pragma unroll
            for (int ns = 0; ns < 8; ns++)
                #pragma unroll
                for (int e = 0; e < 2; e++) {
                    float v = acc[ms][ns][2 * h + e];
                    int n = nq * 64 + ns * 8 + 2 * q + e;
                    if (n != 0 && v > dthr) {
                        int slot = atomicAdd(&S.cnt[r], 1);
                        if (slot < NCAND) S.cand_n[r][slot] = n;
                    }
                }
        }
    __syncthreads();

    // ---- Phase 3: owner warp refines 4 rows with exact f32 dots ----
    #pragma unroll 1
    for (int rr = 0; rr < 4; rr++) {
        int r = w * 4 + rr;
        int cntr = S.cnt[r];
        const float4* q4 = (const float4*)(Qb + r * CCH);

        int bn = 0;
        float bp = 0.f;
        float bd;

        if (cntr <= NCAND) {
            int m = cntr;
            #pragma unroll 1
            for (int i = 0; i < m; i++) {
                int n = S.cand_n[r][i];
                float s = warp_dot256(q4, (const float4*)(P + n * CCH), lane);
                if (lane == 0) S.candd[r][i] = s;
            }
            __syncwarp();

            float dmax = S.candd[r][0];
            for (int i = 1; i < m; i++) dmax = fmaxf(dmax, S.candd[r][i]);
            float Xf = __fdiv_rn(dmax, 0.1f);

            double z = 0.0;
            for (int i = 0; i < m; i++) {
                float x = __fdiv_rn(S.candd[r][i], 0.1f);
                float e = expf(__fsub_rn(x, Xf));
                if (e >= FMINF) z += (double)e;
            }
            float Za = (float)z;

            bd = S.candd[r][0];
            for (int i = 0; i < m; i++) {
                int n = S.cand_n[r][i];
                float d = S.candd[r][i];
                float x = __fdiv_rn(d, 0.1f);
                float e = expf(__fsub_rn(x, Xf));
                if (e < FMINF) e = 0.f;
                float sc = __fdiv_rn(e, Za);
                if (sc < FMINF) sc = 0.f;
                float p = __fmul_rn(sc, S.wS[n]);
                if (p < FMINF) p = 0.f;
                if (p > bp || (p == bp && p > 0.f && n < bn)) {
                    bp = p; bn = n; bd = d;
                }
            }
        } else {
            // overflow: full exact scan of all 512 protos (rare; correct).
            // p_s is dead after the mainloop — reuse column w as dot scratch.
            #pragma unroll 1
            for (int n = 0; n < NN; n++) {
                float s = warp_dot256(q4, (const float4*)(P + n * CCH), lane);
                if (lane == 0) S.p_s[n][w] = s;
            }
            __syncwarp();
            float dmax = -INFINITY;
            for (int n = 0; n < NN; n++) dmax = fmaxf(dmax, S.p_s[n][w]);
            float Xf = __fdiv_rn(dmax, 0.1f);
            double z = 0.0;
            for (int n = 0; n < NN; n++) {
                float x = __fdiv_rn(S.p_s[n][w], 0.1f);
                float e = expf(__fsub_rn(x, Xf));
                if (e >= FMINF) z += (double)e;
            }
            float Za = (float)z;
            bd = S.p_s[0][w];
            for (int n = 0; n < NN; n++) {
                float d = S.p_s[n][w];
                float x = __fdiv_rn(d, 0.1f);
                float e = expf(__fsub_rn(x, Xf));
                if (e < FMINF) e = 0.f;
                float sc = __fdiv_rn(e, Za);
                if (sc < FMINF) sc = 0.f;
                float p = __fmul_rn(sc, S.wS[n]);
                if (p < FMINF) p = 0.f;
                if (p > bp) { bp = p; bn = n; bd = d; }  // ascending n
            }
        }

        if (lane == 0) {
            int row = R0 + r;
            out[row] = fmaf(-2.0f, bd, g_qq[row]) + S.pn2S[bn];
        }
    }
}

// ---------------------------------------------------------------------------
extern "C" void kernel_launch(void* const* d_in, const int* in_sizes, int n_in,
                              void* d_out, int out_size) {
    const float* Q = nullptr;
    const float* P = nullptr;
    const float* G = nullptr;
    for (int i = 0; i < n_in; i++) {
        if (in_sizes[i] == BB * LL * CCH) Q = (const float*)d_in[i];
        else if (in_sizes[i] == NN * CCH) P = (const float*)d_in[i];
        else if (in_sizes[i] == BB * KK * CCH) G = (const float*)d_in[i];
    }
    float* out = (float*)d_out;

    cudaFuncSetAttribute(match_kernel,
                         cudaFuncAttributeMaxDynamicSharedMemorySize,
                         (int)sizeof(SmemT));

    prep_w_kernel<<<BB, 256>>>(P, G);
    prep_pn2_kernel<<<NN / 8, 256>>>(P);
    prep_qq_kernel<<<BB * LL / 8, 256>>>(Q);
    match_kernel<<<BB * LL / 64, 512, sizeof(SmemT)>>>(Q, P, out);
}

// round 9
// speedup vs baseline: 1.5240x; 1.0059x over previous
#include <cuda_runtime.h>
#include <math.h>

#define BB 8
#define LL 8192
#define CCH 256
#define NN 512
#define KK 16
#define FMINF 1.17549435e-38f

// scratch (no allocations allowed)
__device__ float g_w[BB * NN];    // FTZ proto_weights
__device__ float g_t[BB * NN];    // log(w), -inf where 0 (prep only)
__device__ float g_pn2[NN];       // |p_n|^2
__device__ float g_qq[BB * LL];   // |q_l|^2

__device__ __forceinline__ float warp_maxf(float v) {
    #pragma unroll
    for (int o = 16; o; o >>= 1) v = fmaxf(v, __shfl_xor_sync(0xffffffffu, v, o));
    return v;
}
__device__ __forceinline__ float warp_sumf(float v) {
    #pragma unroll
    for (int o = 16; o; o >>= 1) v += __shfl_xor_sync(0xffffffffu, v, o);
    return v;
}
__device__ __forceinline__ double warp_sumd(double v) {
    #pragma unroll
    for (int o = 16; o; o >>= 1) v += __shfl_xor_sync(0xffffffffu, v, o);
    return v;
}

// m16n8k8 TF32 mma (row.col). Raw f32 bits as tf32 (truncation) — candidate
// filter only; margins cover the error.
__device__ __forceinline__ void mma_tf32(float& c0, float& c1, float& c2, float& c3,
                                         float a0, float a1, float a2, float a3,
                                         float b0, float b1) {
    asm volatile(
        "mma.sync.aligned.m16n8k8.row.col.f32.tf32.tf32.f32 "
        "{%0,%1,%2,%3}, {%4,%5,%6,%7}, {%8,%9}, {%0,%1,%2,%3};"
        : "+f"(c0), "+f"(c1), "+f"(c2), "+f"(c3)
        : "r"(__float_as_uint(a0)), "r"(__float_as_uint(a1)),
          "r"(__float_as_uint(a2)), "r"(__float_as_uint(a3)),
          "r"(__float_as_uint(b0)), "r"(__float_as_uint(b1)));
}

__device__ __forceinline__ float dot8(const float4& qa, const float4& qb,
                                      const float4& pa, const float4& pb) {
    float s = 0.f;
    s = fmaf(qa.x, pa.x, s); s = fmaf(qa.y, pa.y, s);
    s = fmaf(qa.z, pa.z, s); s = fmaf(qa.w, pa.w, s);
    s = fmaf(qb.x, pb.x, s); s = fmaf(qb.y, pb.y, s);
    s = fmaf(qb.z, pb.z, s); s = fmaf(qb.w, pb.w, s);
    return s;
}

// ---------------------------------------------------------------------------
// prep kernels (unchanged)
// ---------------------------------------------------------------------------
__global__ void prep_w_kernel(const float* __restrict__ P,
                              const float* __restrict__ gt) {
    int b = blockIdx.x;
    int tid = threadIdx.x;
    int lane = tid & 31, wid = tid >> 5;
    __shared__ double gsd[CCH];
    __shared__ float xs[NN];
    __shared__ float redf[256];
    __shared__ double redd[256];
    __shared__ float sXmax, sZw;

    if (tid < CCH) {
        double s = 0.0;
        #pragma unroll
        for (int k = 0; k < KK; k++) s += (double)gt[(b * KK + k) * CCH + tid];
        gsd[tid] = (double)__fdiv_rn((float)s, 16.0f);
    }
    __syncthreads();

    for (int n = wid; n < NN; n += 8) {
        const float4* pr4 = (const float4*)(P + n * CCH);
        float4 v0 = pr4[lane];
        float4 v1 = pr4[lane + 32];
        int c0 = lane * 4, c1 = 128 + lane * 4;
        double a = 0.0;
        a = fma((double)v0.x, gsd[c0 + 0], a);
        a = fma((double)v0.y, gsd[c0 + 1], a);
        a = fma((double)v0.z, gsd[c0 + 2], a);
        a = fma((double)v0.w, gsd[c0 + 3], a);
        a = fma((double)v1.x, gsd[c1 + 0], a);
        a = fma((double)v1.y, gsd[c1 + 1], a);
        a = fma((double)v1.z, gsd[c1 + 2], a);
        a = fma((double)v1.w, gsd[c1 + 3], a);
        a = warp_sumd(a);
        if (lane == 0) xs[n] = __fdiv_rn((float)a, 0.1f);
    }
    __syncthreads();

    {
        float m = -INFINITY;
        for (int n = tid; n < NN; n += blockDim.x) m = fmaxf(m, xs[n]);
        redf[tid] = m;
        __syncthreads();
        for (int s = 128; s; s >>= 1) {
            if (tid < s) redf[tid] = fmaxf(redf[tid], redf[tid + s]);
            __syncthreads();
        }
        if (tid == 0) sXmax = redf[0];
        __syncthreads();
    }
    float X = sXmax;

    {
        double z = 0.0;
        for (int n = tid; n < NN; n += blockDim.x) {
            float e = expf(__fsub_rn(xs[n], X));
            if (e >= FMINF) z += (double)e;
        }
        redd[tid] = z;
        __syncthreads();
        for (int s = 128; s; s >>= 1) {
            if (tid < s) redd[tid] += redd[tid + s];
            __syncthreads();
        }
        if (tid == 0) sZw = (float)redd[0];
        __syncthreads();
    }
    float Zw = sZw;

    for (int n = tid; n < NN; n += blockDim.x) {
        float e = expf(__fsub_rn(xs[n], X));
        if (e < FMINF) e = 0.f;
        float w = __fdiv_rn(e, Zw);
        if (w < FMINF) w = 0.f;
        g_w[b * NN + n] = w;
        g_t[b * NN + n] = (w > 0.f) ? logf(w) : -INFINITY;
    }
}

__global__ void prep_pn2_kernel(const float* __restrict__ P) {
    int lane = threadIdx.x & 31, wid = threadIdx.x >> 5;
    int n = blockIdx.x * 8 + wid;
    const float4* pr4 = (const float4*)(P + n * CCH);
    float4 a = pr4[lane];
    float4 c = pr4[lane + 32];
    float s = a.x * a.x + a.y * a.y + a.z * a.z + a.w * a.w
            + c.x * c.x + c.y * c.y + c.z * c.z + c.w * c.w;
    s = warp_sumf(s);
    if (lane == 0) g_pn2[n] = s;
}

__global__ void prep_qq_kernel(const float* __restrict__ Q) {
    int wid = threadIdx.x >> 5, lane = threadIdx.x & 31;
    int row = blockIdx.x * 8 + wid;
    const float4* q4 = (const float4*)Q + (size_t)row * (CCH / 4);
    float4 a = q4[lane];
    float4 c = q4[lane + 32];
    float s = a.x * a.x + a.y * a.y + a.z * a.z + a.w * a.w
            + c.x * c.x + c.y * c.y + c.z * c.z + c.w * c.w;
    s = warp_sumf(s);
    if (lane == 0) g_qq[row] = s;
}

// ---------------------------------------------------------------------------
// Main kernel: TF32 mma filter + exact f32 candidate refinement.
// Block = 64 rows x 512 protos, 512 threads (16 warps = 2 L-halves x 8 N-octs).
// Software-pipelined staging (prefetch chunk cc+16 LDGs over chunk cc's mma).
// Candidate rule: approx dot within 9.4 of approx max. Overflow -> full scan.
// ---------------------------------------------------------------------------
#define NCAND 64

struct SmemT {
    float p_s[NN][20];       // swizzled P chunk; reused as scratch in ovf path
    float q_s[64][20];
    float wS[NN], pn2S[NN];
    float dmS[8][64];
    int   cnt[64];
    int   cand_n[64][NCAND];
    float candd[64][NCAND];
};

__global__ void __launch_bounds__(512, 1)
match_kernel(const float* __restrict__ Q, const float* __restrict__ P,
             float* __restrict__ out) {
    extern __shared__ char smem_raw[];
    SmemT& S = *(SmemT*)smem_raw;

    int tid = threadIdx.x;
    int lane = tid & 31, w = tid >> 5;
    int lh = w & 1;
    int nq = w >> 1;
    int g = lane >> 2, q = lane & 3;

    int R0 = blockIdx.x * 64;
    int b = R0 >> 13;

    if (tid < NN) {
        S.wS[tid] = g_w[b * NN + tid];
        S.pn2S[tid] = g_pn2[tid];
    }
    if (tid < 64) { S.cnt[tid] = 1; S.cand_n[tid][0] = 0; }

    const float* Qb = Q + (size_t)R0 * CCH;

    float acc[2][8][4];
    #pragma unroll
    for (int ms = 0; ms < 2; ms++)
        #pragma unroll
        for (int ns = 0; ns < 8; ns++)
            #pragma unroll
            for (int e = 0; e < 4; e++) acc[ms][ns][e] = 0.f;

    // staging registers + invariant indices
    int sn[4], sf[4], ssr[4];
    #pragma unroll
    for (int r = 0; r < 4; r++) {
        int idx = tid + r * 512;
        sn[r] = idx >> 2; sf[r] = idx & 3; ssr[r] = (sn[r] >> 3) & 3;
    }
    int ql = tid >> 2, qf = tid & 3, qsr = (ql >> 3) & 3;

    float4 pv[4], qv;
    // prefetch chunk 0
    #pragma unroll
    for (int r = 0; r < 4; r++)
        pv[r] = *(const float4*)(P + sn[r] * CCH + 0 + 4 * sf[r]);
    if (tid < 256) qv = *(const float4*)(Qb + ql * CCH + 0 + 4 * qf);

    for (int cc = 0; cc < CCH; cc += 16) {
        // store staged chunk (element-transposed swizzle, as round 8)
        #pragma unroll
        for (int r = 0; r < 4; r++) {
            int n = sn[r], f = sf[r], sr = ssr[r];
            S.p_s[n][((0 + sr) & 3) * 4 + f] = pv[r].x;
            S.p_s[n][((1 + sr) & 3) * 4 + f] = pv[r].y;
            S.p_s[n][((2 + sr) & 3) * 4 + f] = pv[r].z;
            S.p_s[n][((3 + sr) & 3) * 4 + f] = pv[r].w;
        }
        if (tid < 256) {
            S.q_s[ql][((0 + qsr) & 3) * 4 + qf] = qv.x;
            S.q_s[ql][((1 + qsr) & 3) * 4 + qf] = qv.y;
            S.q_s[ql][((2 + qsr) & 3) * 4 + qf] = qv.z;
            S.q_s[ql][((3 + qsr) & 3) * 4 + qf] = qv.w;
        }
        __syncthreads();

        // prefetch next chunk (overlaps with mma below)
        if (cc + 16 < CCH) {
            #pragma unroll
            for (int r = 0; r < 4; r++)
                pv[r] = *(const float4*)(P + sn[r] * CCH + (cc + 16) + 4 * sf[r]);
            if (tid < 256)
                qv = *(const float4*)(Qb + ql * CCH + (cc + 16) + 4 * qf);
        }

        float4 A[2][2];
        #pragma unroll
        for (int ms = 0; ms < 2; ms++)
            #pragma unroll
            for (int h = 0; h < 2; h++) {
                int row = lh * 32 + ms * 16 + 8 * h + g;
                int sr = (row >> 3) & 3;
                A[ms][h] = *(const float4*)&S.q_s[row][((q + sr) & 3) * 4];
            }
        #pragma unroll
        for (int ns = 0; ns < 8; ns++) {
            int n = nq * 64 + ns * 8 + g;
            int sr = (n >> 3) & 3;
            float4 Bv = *(const float4*)&S.p_s[n][((q + sr) & 3) * 4];
            #pragma unroll
            for (int ms = 0; ms < 2; ms++) {
                mma_tf32(acc[ms][ns][0], acc[ms][ns][1], acc[ms][ns][2], acc[ms][ns][3],
                         A[ms][0].x, A[ms][1].x, A[ms][0].y, A[ms][1].y, Bv.x, Bv.y);
                mma_tf32(acc[ms][ns][0], acc[ms][ns][1], acc[ms][ns][2], acc[ms][ns][3],
                         A[ms][0].z, A[ms][1].z, A[ms][0].w, A[ms][1].w, Bv.z, Bv.w);
            }
        }
        __syncthreads();
    }

    // ---- Phase 1: per-(octant,row) local max of approx dot ----
    #pragma unroll
    for (int ms = 0; ms < 2; ms++)
        #pragma unroll
        for (int h = 0; h < 2; h++) {
            int r = lh * 32 + ms * 16 + 8 * h + g;
            float vm = -INFINITY;
            #pragma unroll
            for (int ns = 0; ns < 8; ns++)
                #pragma unroll
                for (int e = 0; e < 2; e++)
                    vm = fmaxf(vm, acc[ms][ns][2 * h + e]);
            vm = fmaxf(vm, __shfl_xor_sync(0xffffffffu, vm, 1));
            vm = fmaxf(vm, __shfl_xor_sync(0xffffffffu, vm, 2));
            if (q == 0) S.dmS[nq][r] = vm;
        }
    __syncthreads();

    // ---- Phase 2: candidate push ----
    #pragma unroll
    for (int ms = 0; ms < 2; ms++)
        #pragma unroll
        for (int h = 0; h < 2; h++) {
            int r = lh * 32 + ms * 16 + 8 * h + g;
            float gdm = -INFINITY;
            #pragma unroll
            for (int o = 0; o < 8; o++) gdm = fmaxf(gdm, S.dmS[o][r]);
            float dthr = gdm - 9.4f;
            #pragma unroll
            for (int ns = 0; ns < 8; ns++)
                #pragma unroll
                for (int e = 0; e < 2; e++) {
                    float v = acc[ms][ns][2 * h + e];
                    int n = nq * 64 + ns * 8 + 2 * q + e;
                    if (n != 0 && v > dthr) {
                        int slot = atomicAdd(&S.cnt[r], 1);
                        if (slot < NCAND) S.cand_n[r][slot] = n;
                    }
                }
        }
    __syncthreads();

    // ---- Phase 3: owner warp refines 4 rows; candidate dots batched 4-wide ----
    #pragma unroll 1
    for (int rr = 0; rr < 4; rr++) {
        int r = w * 4 + rr;
        int cntr = S.cnt[r];
        const float4* q4 = (const float4*)(Qb + r * CCH);

        int bn = 0;
        float bp = 0.f;
        float bd;

        if (cntr <= NCAND) {
            int m = cntr;
            float4 qa = q4[lane], qb = q4[lane + 32];

            #pragma unroll 1
            for (int i0 = 0; i0 < m; i0 += 4) {
                int mm = min(4, m - i0);
                float4 pa[4], pb[4];
                #pragma unroll
                for (int j = 0; j < 4; j++)
                    if (j < mm) {
                        const float4* p4 =
                            (const float4*)(P + S.cand_n[r][i0 + j] * CCH);
                        pa[j] = p4[lane];
                        pb[j] = p4[lane + 32];
                    }
                float s[4];
                #pragma unroll
                for (int j = 0; j < 4; j++)
                    if (j < mm) s[j] = dot8(qa, qb, pa[j], pb[j]);
                #pragma unroll
                for (int o = 16; o; o >>= 1)
                    #pragma unroll
                    for (int j = 0; j < 4; j++)
                        if (j < mm) s[j] += __shfl_xor_sync(0xffffffffu, s[j], o);
                if (lane == 0)
                    #pragma unroll
                    for (int j = 0; j < 4; j++)
                        if (j < mm) S.candd[r][i0 + j] = s[j];
            }
            __syncwarp();

            float dmax = S.candd[r][0];
            for (int i = 1; i < m; i++) dmax = fmaxf(dmax, S.candd[r][i]);
            float Xf = __fdiv_rn(dmax, 0.1f);

            double z = 0.0;
            for (int i = 0; i < m; i++) {
                float x = __fdiv_rn(S.candd[r][i], 0.1f);
                float e = expf(__fsub_rn(x, Xf));
                if (e >= FMINF) z += (double)e;
            }
            float Za = (float)z;

            bd = S.candd[r][0];
            for (int i = 0; i < m; i++) {
                int n = S.cand_n[r][i];
                float d = S.candd[r][i];
                float x = __fdiv_rn(d, 0.1f);
                float e = expf(__fsub_rn(x, Xf));
                if (e < FMINF) e = 0.f;
                float sc = __fdiv_rn(e, Za);
                if (sc < FMINF) sc = 0.f;
                float p = __fmul_rn(sc, S.wS[n]);
                if (p < FMINF) p = 0.f;
                if (p > bp || (p == bp && p > 0.f && n < bn)) {
                    bp = p; bn = n; bd = d;
                }
            }
        } else {
            // overflow: full exact scan of all 512 protos (rare; correct).
            #pragma unroll 1
            for (int n = 0; n < NN; n++) {
                const float4* p4 = (const float4*)(P + n * CCH);
                float s = warp_sumf(dot8(q4[lane], q4[lane + 32],
                                         p4[lane], p4[lane + 32]));
                if (lane == 0) S.p_s[n][w] = s;
            }
            __syncwarp();
            float dmax = -INFINITY;
            for (int n = 0; n < NN; n++) dmax = fmaxf(dmax, S.p_s[n][w]);
            float Xf = __fdiv_rn(dmax, 0.1f);
            double z = 0.0;
            for (int n = 0; n < NN; n++) {
                float x = __fdiv_rn(S.p_s[n][w], 0.1f);
                float e = expf(__fsub_rn(x, Xf));
                if (e >= FMINF) z += (double)e;
            }
            float Za = (float)z;
            bd = S.p_s[0][w];
            for (int n = 0; n < NN; n++) {
                float d = S.p_s[n][w];
                float x = __fdiv_rn(d, 0.1f);
                float e = expf(__fsub_rn(x, Xf));
                if (e < FMINF) e = 0.f;
                float sc = __fdiv_rn(e, Za);
                if (sc < FMINF) sc = 0.f;
                float p = __fmul_rn(sc, S.wS[n]);
                if (p < FMINF) p = 0.f;
                if (p > bp) { bp = p; bn = n; bd = d; }
            }
        }

        if (lane == 0) {
            int row = R0 + r;
            out[row] = fmaf(-2.0f, bd, g_qq[row]) + S.pn2S[bn];
        }
    }
}

// ---------------------------------------------------------------------------
extern "C" void kernel_launch(void* const* d_in, const int* in_sizes, int n_in,
                              void* d_out, int out_size) {
    const float* Q = nullptr;
    const float* P = nullptr;
    const float* G = nullptr;
    for (int i = 0; i < n_in; i++) {
        if (in_sizes[i] == BB * LL * CCH) Q = (const float*)d_in[i];
        else if (in_sizes[i] == NN * CCH) P = (const float*)d_in[i];
        else if (in_sizes[i] == BB * KK * CCH) G = (const float*)d_in[i];
    }
    float* out = (float*)d_out;

    cudaFuncSetAttribute(match_kernel,
                         cudaFuncAttributeMaxDynamicSharedMemorySize,
                         (int)sizeof(SmemT));

    prep_w_kernel<<<BB, 256>>>(P, G);
    prep_pn2_kernel<<<NN / 8, 256>>>(P);
    prep_qq_kernel<<<BB * LL / 8, 256>>>(Q);
    match_kernel<<<BB * LL / 64, 512, sizeof(SmemT)>>>(Q, P, out);
}